// round 3
// baseline (speedup 1.0000x reference)
#include <cuda_runtime.h>
#include <cuda_bf16.h>

// ---------------- problem constants ----------------
#define BB 8
#define NN 131072
#define SS 1024
#define KK 64
#define CC 32
#define HH 64          // 2*C
#define D1 38          // C + 6
#define D2 70          // H + 6
#define H3 256         // 4*H

// output layout (flattened concat of the 4 returned tensors)
#define OFF_LOCS  0
#define OFF_OUT   (BB*SS*3)                  // 24576
#define OFF_BOXES (OFF_OUT + BB*HH*SS)       // 548864
#define OFF_INDS  (OFF_BOXES + BB*SS*6)      // 598016

// ---------------- scratch (device globals; no allocation allowed) ----------
__device__ float g_feats_nc[BB * NN * CC];   // [B,N,C] transposed feats (~134MB)
__device__ float g_dimbox  [BB * NN * 3];    // per-point box dims
__device__ float g_fps_locs[BB * SS * 3];
__device__ float g_fps_dim [BB * SS * 3];
__device__ float g_newfeat [BB * SS * HH];   // stage1 output == identity
__device__ float g_h2max   [BB * SS * HH];   // stage2 output

// ---------------- prep: transpose feats, compute dim boxes ----------------
__global__ __launch_bounds__(256) void prep_kernel(
    const float* __restrict__ feats, const float* __restrict__ boxes)
{
    int idx = blockIdx.x * blockDim.x + threadIdx.x;   // over B*N
    if (idx >= BB * NN) return;
    int b = idx >> 17;             // N = 2^17
    int n = idx & (NN - 1);

    float tmp[CC];
    #pragma unroll
    for (int c = 0; c < CC; c++)
        tmp[c] = feats[(b * CC + c) * NN + n];         // coalesced across threads

    float4* dst = (float4*)(g_feats_nc + (idx << 5));
    #pragma unroll
    for (int q = 0; q < 8; q++)
        dst[q] = make_float4(tmp[4*q], tmp[4*q+1], tmp[4*q+2], tmp[4*q+3]);

    const float* bx = boxes + idx * 6;
    float* dd = g_dimbox + idx * 3;
    dd[0] = bx[3] - bx[0];
    dd[1] = bx[4] - bx[1];
    dd[2] = bx[5] - bx[2];
}

// ---------------- fps gather: fills scratch + 3 output sections ----------
__global__ __launch_bounds__(256) void fps_kernel(
    const float* __restrict__ locs, const float* __restrict__ boxes,
    const int* __restrict__ fps_inds, float* __restrict__ out)
{
    int idx = blockIdx.x * blockDim.x + threadIdx.x;   // over B*S
    if (idx >= BB * SS) return;
    int b = idx >> 10;
    int j = fps_inds[idx];

    const float* lp = locs + (b * NN + j) * 3;
    float l0 = lp[0], l1 = lp[1], l2 = lp[2];
    g_fps_locs[idx*3+0] = l0; g_fps_locs[idx*3+1] = l1; g_fps_locs[idx*3+2] = l2;
    out[OFF_LOCS + idx*3 + 0] = l0;
    out[OFF_LOCS + idx*3 + 1] = l1;
    out[OFF_LOCS + idx*3 + 2] = l2;

    const float* bx = boxes + (b * NN + j) * 6;
    float b0 = bx[0], b1 = bx[1], b2 = bx[2], b3 = bx[3], b4 = bx[4], b5 = bx[5];
    g_fps_dim[idx*3+0] = b3 - b0;
    g_fps_dim[idx*3+1] = b4 - b1;
    g_fps_dim[idx*3+2] = b5 - b2;
    out[OFF_BOXES + idx*6 + 0] = b0;
    out[OFF_BOXES + idx*6 + 1] = b1;
    out[OFF_BOXES + idx*6 + 2] = b2;
    out[OFF_BOXES + idx*6 + 3] = b3;
    out[OFF_BOXES + idx*6 + 4] = b4;
    out[OFF_BOXES + idx*6 + 5] = b5;

    out[OFF_INDS + idx] = (float)j;
}

// ---------------- stage 1: gather K neighbors, mlp1a+mlp1b, max ----------
__global__ __launch_bounds__(64) void stage1_kernel(
    const float* __restrict__ locs, const int* __restrict__ nbr,
    const float* __restrict__ w1a, const float* __restrict__ s1a, const float* __restrict__ t1a,
    const float* __restrict__ w1b, const float* __restrict__ s1b, const float* __restrict__ t1b)
{
    __shared__ __align__(16) float sw1a[D1 * CC];
    __shared__ float sb1a[CC];
    __shared__ __align__(16) float sw1b[CC * HH];
    __shared__ float sb1b[HH];
    __shared__ float sh[KK * 65];

    int tid = threadIdx.x;
    int bs  = blockIdx.x;            // b*S + s
    int b   = bs >> 10;

    for (int i = tid; i < D1 * CC; i += 64) sw1a[i] = w1a[i] * s1a[i & 31];
    for (int i = tid; i < CC * HH; i += 64) sw1b[i] = w1b[i] * s1b[i & 63];
    if (tid < CC) sb1a[tid] = t1a[tid];
    sb1b[tid] = t1b[tid];
    __syncthreads();

    int j = nbr[bs * KK + tid];

    float g[D1];
    {
        const float* lp = locs + (b * NN + j) * 3;
        g[0] = (lp[0] - g_fps_locs[bs*3+0]) * 2.5f;
        g[1] = (lp[1] - g_fps_locs[bs*3+1]) * 2.5f;
        g[2] = (lp[2] - g_fps_locs[bs*3+2]) * 2.5f;
        const float* dp = g_dimbox + (b * NN + j) * 3;
        g[3] = fabsf(dp[0] - g_fps_dim[bs*3+0]);
        g[4] = fabsf(dp[1] - g_fps_dim[bs*3+1]);
        g[5] = fabsf(dp[2] - g_fps_dim[bs*3+2]);
        const float4* fp = (const float4*)(g_feats_nc + ((b * NN + j) << 5));
        #pragma unroll
        for (int q = 0; q < 8; q++) {
            float4 v = fp[q];
            g[6+4*q+0] = v.x; g[6+4*q+1] = v.y; g[6+4*q+2] = v.z; g[6+4*q+3] = v.w;
        }
    }

    // mlp1a: 38 -> 32, relu
    float h1[CC];
    #pragma unroll
    for (int c = 0; c < CC; c++) h1[c] = sb1a[c];
    #pragma unroll
    for (int i = 0; i < D1; i++) {
        float gv = g[i];
        const float4* w = (const float4*)(sw1a + i * CC);
        #pragma unroll
        for (int c4 = 0; c4 < CC/4; c4++) {
            float4 wv = w[c4];
            h1[4*c4+0] += gv * wv.x;
            h1[4*c4+1] += gv * wv.y;
            h1[4*c4+2] += gv * wv.z;
            h1[4*c4+3] += gv * wv.w;
        }
    }
    #pragma unroll
    for (int c = 0; c < CC; c++) h1[c] = fmaxf(h1[c], 0.0f);

    // mlp1b: 32 -> 64, relu
    float h2[HH];
    #pragma unroll
    for (int c = 0; c < HH; c++) h2[c] = sb1b[c];
    #pragma unroll
    for (int i = 0; i < CC; i++) {
        float gv = h1[i];
        const float4* w = (const float4*)(sw1b + i * HH);
        #pragma unroll
        for (int c4 = 0; c4 < HH/4; c4++) {
            float4 wv = w[c4];
            h2[4*c4+0] += gv * wv.x;
            h2[4*c4+1] += gv * wv.y;
            h2[4*c4+2] += gv * wv.z;
            h2[4*c4+3] += gv * wv.w;
        }
    }
    #pragma unroll
    for (int c = 0; c < HH; c++) sh[tid * 65 + c] = fmaxf(h2[c], 0.0f);
    __syncthreads();

    // max over K: thread = channel
    float m = sh[tid];
    #pragma unroll 8
    for (int k = 1; k < KK; k++) m = fmaxf(m, sh[k * 65 + tid]);
    g_newfeat[bs * HH + tid] = m;
}

// ---------------- stage 2: gather K2 fps-neighbors, mlp2 (no relu), max --
#define ACC2(i_, gv_) do {                                          \
    float gv = (gv_);                                               \
    const float4* w = (const float4*)(sw2 + (i_) * HH);             \
    _Pragma("unroll")                                               \
    for (int c4 = 0; c4 < HH/4; c4++) {                             \
        float4 wv = w[c4];                                          \
        h[4*c4+0] += gv * wv.x;                                     \
        h[4*c4+1] += gv * wv.y;                                     \
        h[4*c4+2] += gv * wv.z;                                     \
        h[4*c4+3] += gv * wv.w;                                     \
    }                                                               \
} while (0)

__global__ __launch_bounds__(64) void stage2_kernel(
    const int* __restrict__ nbr2,
    const float* __restrict__ w2, const float* __restrict__ s2, const float* __restrict__ t2)
{
    __shared__ __align__(16) float sw2[D2 * HH];
    __shared__ float sb2[HH];
    __shared__ float sh[KK * 65];

    int tid = threadIdx.x;
    int bs  = blockIdx.x;
    int b   = bs >> 10;

    for (int i = tid; i < D2 * HH; i += 64) sw2[i] = w2[i] * s2[i & 63];
    sb2[tid] = t2[tid];
    __syncthreads();

    int j  = nbr2[bs * KK + tid];      // index into fps set (0..S-1)
    int fj = (b << 10) + j;

    float h[HH];
    #pragma unroll
    for (int c = 0; c < HH; c++) h[c] = sb2[c];

    ACC2(0, (g_fps_locs[fj*3+0] - g_fps_locs[bs*3+0]) * 1.25f);
    ACC2(1, (g_fps_locs[fj*3+1] - g_fps_locs[bs*3+1]) * 1.25f);
    ACC2(2, (g_fps_locs[fj*3+2] - g_fps_locs[bs*3+2]) * 1.25f);
    ACC2(3, fabsf(g_fps_dim[fj*3+0] - g_fps_dim[bs*3+0]));
    ACC2(4, fabsf(g_fps_dim[fj*3+1] - g_fps_dim[bs*3+1]));
    ACC2(5, fabsf(g_fps_dim[fj*3+2] - g_fps_dim[bs*3+2]));

    const float4* fp = (const float4*)(g_newfeat + fj * HH);
    #pragma unroll
    for (int q = 0; q < HH/4; q++) {
        float4 v = fp[q];
        ACC2(6 + 4*q + 0, v.x);
        ACC2(6 + 4*q + 1, v.y);
        ACC2(6 + 4*q + 2, v.z);
        ACC2(6 + 4*q + 3, v.w);
    }

    #pragma unroll
    for (int c = 0; c < HH; c++) sh[tid * 65 + c] = h[c];   // no relu
    __syncthreads();

    float m = sh[tid];
    #pragma unroll 8
    for (int k = 1; k < KK; k++) m = fmaxf(m, sh[k * 65 + tid]);
    g_h2max[bs * HH + tid] = m;
}

// ---------------- stage 3: bottleneck mlp3 + skip, write transposed ------
#define TS 16
__global__ __launch_bounds__(256) void stage3_kernel(
    const float* __restrict__ w3a, const float* __restrict__ s3a, const float* __restrict__ t3a,
    const float* __restrict__ w3b, const float* __restrict__ s3b, const float* __restrict__ t3b,
    float* __restrict__ out)
{
    __shared__ float h2s[TS * HH];    // 4KB
    __shared__ float h3s[TS * H3];    // 16KB
    int t = threadIdx.x;
    int row0 = blockIdx.x * TS;

    for (int i = t; i < TS * HH; i += 256) h2s[i] = g_h2max[row0 * HH + i];
    __syncthreads();

    // phase A: h3a = relu(h2 @ (w3a*s3a) + t3a); thread t owns column t
    {
        float sc = s3a[t], bi = t3a[t];
        float acc[TS];
        #pragma unroll
        for (int r = 0; r < TS; r++) acc[r] = bi;
        #pragma unroll 4
        for (int i = 0; i < HH; i++) {
            float wv = w3a[i * H3 + t] * sc;
            #pragma unroll
            for (int r = 0; r < TS; r++) acc[r] += h2s[r * HH + i] * wv;
        }
        #pragma unroll
        for (int r = 0; r < TS; r++) h3s[r * H3 + t] = fmaxf(acc[r], 0.0f);
    }
    __syncthreads();

    // phase B: h3b = h3a @ (w3b*s3b) + t3b ; out = relu(h3b + identity)
    {
        int c  = t & 63;
        int rg = t >> 6;          // 0..3, each thread does 4 rows
        float sc = s3b[c], bi = t3b[c];
        float acc[4];
        #pragma unroll
        for (int rr = 0; rr < 4; rr++) acc[rr] = bi;
        #pragma unroll 4
        for (int i = 0; i < H3; i++) {
            float wv = w3b[i * HH + c] * sc;
            #pragma unroll
            for (int rr = 0; rr < 4; rr++)
                acc[rr] += h3s[(rg * 4 + rr) * H3 + i] * wv;
        }
        #pragma unroll
        for (int rr = 0; rr < 4; rr++) {
            int row = row0 + rg * 4 + rr;
            int b = row >> 10, s = row & 1023;
            float v = acc[rr] + g_newfeat[row * HH + c];
            out[OFF_OUT + ((b * HH + c) << 10) + s] = fmaxf(v, 0.0f);
        }
    }
}

// ---------------- launch ----------------
extern "C" void kernel_launch(void* const* d_in, const int* in_sizes, int n_in,
                              void* d_out, int out_size)
{
    const float* locs  = (const float*)d_in[0];
    const float* feats = (const float*)d_in[1];
    const float* boxes = (const float*)d_in[2];
    const int*   fps   = (const int*)d_in[3];
    const int*   nbr   = (const int*)d_in[4];
    const int*   nbr2  = (const int*)d_in[5];
    const float* w1a = (const float*)d_in[6];
    const float* s1a = (const float*)d_in[7];
    const float* t1a = (const float*)d_in[8];
    const float* w1b = (const float*)d_in[9];
    const float* s1b = (const float*)d_in[10];
    const float* t1b = (const float*)d_in[11];
    const float* w2  = (const float*)d_in[12];
    const float* s2  = (const float*)d_in[13];
    const float* t2  = (const float*)d_in[14];
    const float* w3a = (const float*)d_in[15];
    const float* s3a = (const float*)d_in[16];
    const float* t3a = (const float*)d_in[17];
    const float* w3b = (const float*)d_in[18];
    const float* s3b = (const float*)d_in[19];
    const float* t3b = (const float*)d_in[20];
    float* out = (float*)d_out;

    prep_kernel<<<(BB * NN + 255) / 256, 256>>>(feats, boxes);
    fps_kernel<<<(BB * SS + 255) / 256, 256>>>(locs, boxes, fps, out);
    stage1_kernel<<<BB * SS, 64>>>(locs, nbr, w1a, s1a, t1a, w1b, s1b, t1b);
    stage2_kernel<<<BB * SS, 64>>>(nbr2, w2, s2, t2);
    stage3_kernel<<<(BB * SS) / TS, 256>>>(w3a, s3a, t3a, w3b, s3b, t3b, out);
}

// round 4
// speedup vs baseline: 1.1431x; 1.1431x over previous
#include <cuda_runtime.h>
#include <cuda_bf16.h>

// ---------------- problem constants ----------------
#define BB 8
#define NN 131072
#define SS 1024
#define KK 64
#define CC 32
#define HH 64          // 2*C
#define D1 38          // C + 6
#define D2 70          // H + 6
#define H3 256         // 4*H

// output layout (flattened concat of the 4 returned tensors)
#define OFF_LOCS  0
#define OFF_OUT   (BB*SS*3)                  // 24576
#define OFF_BOXES (OFF_OUT + BB*HH*SS)       // 548864
#define OFF_INDS  (OFF_BOXES + BB*SS*6)      // 598016

typedef unsigned long long ull;

// ---------------- f32x2 packed helpers (sm_100+) ----------------
__device__ __forceinline__ ull pack2(float lo, float hi) {
    ull r; asm("mov.b64 %0, {%1, %2};" : "=l"(r) : "f"(lo), "f"(hi)); return r;
}
__device__ __forceinline__ void unpack2(ull v, float& lo, float& hi) {
    asm("mov.b64 {%0, %1}, %2;" : "=f"(lo), "=f"(hi) : "l"(v));
}
__device__ __forceinline__ void fma2(ull& d, ull a, ull b) {
    asm("fma.rn.f32x2 %0, %1, %2, %0;" : "+l"(d) : "l"(a), "l"(b));
}

// ---------------- scratch (device globals; no allocation allowed) ----------
__device__ float g_feats_nc[BB * NN * CC];   // [B,N,C] transposed feats
__device__ float g_dimbox  [BB * NN * 3];
__device__ float g_fps_locs[BB * SS * 3];
__device__ float g_fps_dim [BB * SS * 3];
__device__ float g_newfeat [BB * SS * HH];   // stage1 output == identity
__device__ float g_h2max   [BB * SS * HH];   // stage2 output

// ---------------- prep: transpose feats, compute dim boxes ----------------
__global__ __launch_bounds__(256) void prep_kernel(
    const float* __restrict__ feats, const float* __restrict__ boxes)
{
    int idx = blockIdx.x * blockDim.x + threadIdx.x;   // over B*N
    if (idx >= BB * NN) return;
    int b = idx >> 17;
    int n = idx & (NN - 1);

    float tmp[CC];
    #pragma unroll
    for (int c = 0; c < CC; c++)
        tmp[c] = feats[(b * CC + c) * NN + n];

    float4* dst = (float4*)(g_feats_nc + ((size_t)idx << 5));
    #pragma unroll
    for (int q = 0; q < 8; q++)
        dst[q] = make_float4(tmp[4*q], tmp[4*q+1], tmp[4*q+2], tmp[4*q+3]);

    const float* bx = boxes + (size_t)idx * 6;
    float* dd = g_dimbox + (size_t)idx * 3;
    dd[0] = bx[3] - bx[0];
    dd[1] = bx[4] - bx[1];
    dd[2] = bx[5] - bx[2];
}

// ---------------- fps gather ----------
__global__ __launch_bounds__(256) void fps_kernel(
    const float* __restrict__ locs, const float* __restrict__ boxes,
    const int* __restrict__ fps_inds, float* __restrict__ out)
{
    int idx = blockIdx.x * blockDim.x + threadIdx.x;   // over B*S
    if (idx >= BB * SS) return;
    int b = idx >> 10;
    int j = fps_inds[idx];

    const float* lp = locs + ((size_t)b * NN + j) * 3;
    float l0 = lp[0], l1 = lp[1], l2 = lp[2];
    g_fps_locs[idx*3+0] = l0; g_fps_locs[idx*3+1] = l1; g_fps_locs[idx*3+2] = l2;
    out[OFF_LOCS + idx*3 + 0] = l0;
    out[OFF_LOCS + idx*3 + 1] = l1;
    out[OFF_LOCS + idx*3 + 2] = l2;

    const float* bx = boxes + ((size_t)b * NN + j) * 6;
    float b0 = bx[0], b1 = bx[1], b2 = bx[2], b3 = bx[3], b4 = bx[4], b5 = bx[5];
    g_fps_dim[idx*3+0] = b3 - b0;
    g_fps_dim[idx*3+1] = b4 - b1;
    g_fps_dim[idx*3+2] = b5 - b2;
    out[OFF_BOXES + idx*6 + 0] = b0;
    out[OFF_BOXES + idx*6 + 1] = b1;
    out[OFF_BOXES + idx*6 + 2] = b2;
    out[OFF_BOXES + idx*6 + 3] = b3;
    out[OFF_BOXES + idx*6 + 4] = b4;
    out[OFF_BOXES + idx*6 + 5] = b5;

    out[OFF_INDS + idx] = (float)j;
}

// ================= stage 1: gather K neighbors, mlp1a+mlp1b, max =========
// Block = 1 query, 64 threads. Tiled GEMM in smem, f32x2 packed FMA.
__global__ __launch_bounds__(64) void stage1_kernel(
    const float* __restrict__ locs, const int* __restrict__ nbr,
    const float* __restrict__ w1a, const float* __restrict__ s1a, const float* __restrict__ t1a,
    const float* __restrict__ w1b, const float* __restrict__ s1b, const float* __restrict__ t1b)
{
    __shared__ __align__(16) float wa_s[D1 * CC];    // 4864 B
    __shared__ __align__(16) float wb_s[CC * HH];    // 8192 B
    __shared__ __align__(16) float g1_s[D1 * 64];    // [i][n] 9728 B
    __shared__ __align__(16) float h1_s[CC * 68];    // [c][n] padded 8704 B
    __shared__ float ba_s[CC];
    __shared__ float bb_s[HH];
    __shared__ float red[8 * 68];

    int tid = threadIdx.x;
    int bs  = blockIdx.x;
    int b   = bs >> 10;

    for (int i = tid; i < D1 * CC; i += 64) wa_s[i] = w1a[i] * s1a[i & 31];
    for (int i = tid; i < CC * HH; i += 64) wb_s[i] = w1b[i] * s1b[i & 63];
    if (tid < CC) ba_s[tid] = t1a[tid];
    bb_s[tid] = t1b[tid];

    // ---- fill g1_s[i][n]: thread = neighbor ----
    {
        int j = nbr[bs * KK + tid];
        const float* lp = locs + ((size_t)b * NN + j) * 3;
        g1_s[0*64 + tid] = (lp[0] - g_fps_locs[bs*3+0]) * 2.5f;
        g1_s[1*64 + tid] = (lp[1] - g_fps_locs[bs*3+1]) * 2.5f;
        g1_s[2*64 + tid] = (lp[2] - g_fps_locs[bs*3+2]) * 2.5f;
        const float* dp = g_dimbox + ((size_t)b * NN + j) * 3;
        g1_s[3*64 + tid] = fabsf(dp[0] - g_fps_dim[bs*3+0]);
        g1_s[4*64 + tid] = fabsf(dp[1] - g_fps_dim[bs*3+1]);
        g1_s[5*64 + tid] = fabsf(dp[2] - g_fps_dim[bs*3+2]);
        const float4* fp = (const float4*)(g_feats_nc + (((size_t)b * NN + j) << 5));
        #pragma unroll
        for (int q = 0; q < 8; q++) {
            float4 v = fp[q];
            g1_s[(6+4*q+0)*64 + tid] = v.x;
            g1_s[(6+4*q+1)*64 + tid] = v.y;
            g1_s[(6+4*q+2)*64 + tid] = v.z;
            g1_s[(6+4*q+3)*64 + tid] = v.w;
        }
    }
    __syncthreads();

    int ngrp = tid & 7, cgrp = tid >> 3;
    int n0 = ngrp * 8;

    // ---- GEMM A: 38 -> 32, relu. Tile 8n x 4c. ----
    {
        int c0 = cgrp * 4;
        ull acc[8][2];
        ull bi0 = pack2(ba_s[c0+0], ba_s[c0+1]);
        ull bi1 = pack2(ba_s[c0+2], ba_s[c0+3]);
        #pragma unroll
        for (int n = 0; n < 8; n++) { acc[n][0] = bi0; acc[n][1] = bi1; }

        #pragma unroll 2
        for (int i = 0; i < D1; i++) {
            const float* gr = g1_s + i * 64 + n0;
            float4 ga = *(const float4*)gr;
            float4 gb = *(const float4*)(gr + 4);
            ulonglong2 wv = *(const ulonglong2*)(wa_s + i * CC + c0);
            ull g2[8] = { pack2(ga.x,ga.x), pack2(ga.y,ga.y), pack2(ga.z,ga.z), pack2(ga.w,ga.w),
                          pack2(gb.x,gb.x), pack2(gb.y,gb.y), pack2(gb.z,gb.z), pack2(gb.w,gb.w) };
            #pragma unroll
            for (int n = 0; n < 8; n++) {
                fma2(acc[n][0], g2[n], wv.x);
                fma2(acc[n][1], g2[n], wv.y);
            }
        }
        #pragma unroll
        for (int n = 0; n < 8; n++) {
            float v0, v1, v2, v3;
            unpack2(acc[n][0], v0, v1);
            unpack2(acc[n][1], v2, v3);
            h1_s[(c0+0)*68 + n0 + n] = fmaxf(v0, 0.0f);
            h1_s[(c0+1)*68 + n0 + n] = fmaxf(v1, 0.0f);
            h1_s[(c0+2)*68 + n0 + n] = fmaxf(v2, 0.0f);
            h1_s[(c0+3)*68 + n0 + n] = fmaxf(v3, 0.0f);
        }
    }
    __syncthreads();

    // ---- GEMM B: 32 -> 64, relu, max over K. Tile 8n x 8c. ----
    {
        int c0 = cgrp * 8;
        ull acc[8][4];
        ull bi[4];
        #pragma unroll
        for (int p = 0; p < 4; p++) bi[p] = pack2(bb_s[c0+2*p], bb_s[c0+2*p+1]);
        #pragma unroll
        for (int n = 0; n < 8; n++)
            #pragma unroll
            for (int p = 0; p < 4; p++) acc[n][p] = bi[p];

        #pragma unroll 2
        for (int i = 0; i < CC; i++) {
            const float* gr = h1_s + i * 68 + n0;
            float4 ga = *(const float4*)gr;
            float4 gb = *(const float4*)(gr + 4);
            ulonglong2 wv0 = *(const ulonglong2*)(wb_s + i * HH + c0);
            ulonglong2 wv1 = *(const ulonglong2*)(wb_s + i * HH + c0 + 4);
            ull w[4] = { wv0.x, wv0.y, wv1.x, wv1.y };
            ull g2[8] = { pack2(ga.x,ga.x), pack2(ga.y,ga.y), pack2(ga.z,ga.z), pack2(ga.w,ga.w),
                          pack2(gb.x,gb.x), pack2(gb.y,gb.y), pack2(gb.z,gb.z), pack2(gb.w,gb.w) };
            #pragma unroll
            for (int n = 0; n < 8; n++)
                #pragma unroll
                for (int p = 0; p < 4; p++) fma2(acc[n][p], g2[n], w[p]);
        }

        // local max over the 8 register-resident neighbors (relu deferred: monotone)
        float m[8];
        #pragma unroll
        for (int p = 0; p < 4; p++) unpack2(acc[0][p], m[2*p], m[2*p+1]);
        #pragma unroll
        for (int n = 1; n < 8; n++)
            #pragma unroll
            for (int p = 0; p < 4; p++) {
                float lo, hi; unpack2(acc[n][p], lo, hi);
                m[2*p]   = fmaxf(m[2*p], lo);
                m[2*p+1] = fmaxf(m[2*p+1], hi);
            }
        #pragma unroll
        for (int j = 0; j < 8; j++) red[ngrp * 68 + c0 + j] = m[j];
    }
    __syncthreads();

    float mm = red[tid];
    #pragma unroll
    for (int r = 1; r < 8; r++) mm = fmaxf(mm, red[r * 68 + tid]);
    g_newfeat[bs * HH + tid] = fmaxf(mm, 0.0f);
}

// ================= stage 2: gather K2 fps-neighbors, mlp2, max ===========
__global__ __launch_bounds__(64) void stage2_kernel(
    const int* __restrict__ nbr2,
    const float* __restrict__ w2, const float* __restrict__ s2, const float* __restrict__ t2)
{
    __shared__ __align__(16) float w_s[D2 * HH];   // 17920 B
    __shared__ __align__(16) float g_s[D2 * 64];   // [i][n] 17920 B
    __shared__ float sb[HH];
    __shared__ float red[8 * 68];

    int tid = threadIdx.x;
    int bs  = blockIdx.x;
    int b   = bs >> 10;

    for (int i = tid; i < D2 * HH; i += 64) w_s[i] = w2[i] * s2[i & 63];
    sb[tid] = t2[tid];

    // ---- fill g_s[i][n]: thread = neighbor ----
    {
        int j  = nbr2[bs * KK + tid];
        int fj = (b << 10) + j;
        g_s[0*64 + tid] = (g_fps_locs[fj*3+0] - g_fps_locs[bs*3+0]) * 1.25f;
        g_s[1*64 + tid] = (g_fps_locs[fj*3+1] - g_fps_locs[bs*3+1]) * 1.25f;
        g_s[2*64 + tid] = (g_fps_locs[fj*3+2] - g_fps_locs[bs*3+2]) * 1.25f;
        g_s[3*64 + tid] = fabsf(g_fps_dim[fj*3+0] - g_fps_dim[bs*3+0]);
        g_s[4*64 + tid] = fabsf(g_fps_dim[fj*3+1] - g_fps_dim[bs*3+1]);
        g_s[5*64 + tid] = fabsf(g_fps_dim[fj*3+2] - g_fps_dim[bs*3+2]);
        const float4* fp = (const float4*)(g_newfeat + (size_t)fj * HH);
        #pragma unroll
        for (int q = 0; q < 16; q++) {
            float4 v = fp[q];
            g_s[(6+4*q+0)*64 + tid] = v.x;
            g_s[(6+4*q+1)*64 + tid] = v.y;
            g_s[(6+4*q+2)*64 + tid] = v.z;
            g_s[(6+4*q+3)*64 + tid] = v.w;
        }
    }
    __syncthreads();

    int ngrp = tid & 7, cgrp = tid >> 3;
    int n0 = ngrp * 8, c0 = cgrp * 8;

    ull acc[8][4];
    {
        ull bi[4];
        #pragma unroll
        for (int p = 0; p < 4; p++) bi[p] = pack2(sb[c0+2*p], sb[c0+2*p+1]);
        #pragma unroll
        for (int n = 0; n < 8; n++)
            #pragma unroll
            for (int p = 0; p < 4; p++) acc[n][p] = bi[p];
    }

    #pragma unroll 2
    for (int i = 0; i < D2; i++) {
        const float* gr = g_s + i * 64 + n0;
        float4 ga = *(const float4*)gr;
        float4 gb = *(const float4*)(gr + 4);
        ulonglong2 wv0 = *(const ulonglong2*)(w_s + i * HH + c0);
        ulonglong2 wv1 = *(const ulonglong2*)(w_s + i * HH + c0 + 4);
        ull w[4] = { wv0.x, wv0.y, wv1.x, wv1.y };
        ull g2[8] = { pack2(ga.x,ga.x), pack2(ga.y,ga.y), pack2(ga.z,ga.z), pack2(ga.w,ga.w),
                      pack2(gb.x,gb.x), pack2(gb.y,gb.y), pack2(gb.z,gb.z), pack2(gb.w,gb.w) };
        #pragma unroll
        for (int n = 0; n < 8; n++)
            #pragma unroll
            for (int p = 0; p < 4; p++) fma2(acc[n][p], g2[n], w[p]);
    }

    // max over 8 local neighbors (no relu in stage 2)
    float m[8];
    #pragma unroll
    for (int p = 0; p < 4; p++) unpack2(acc[0][p], m[2*p], m[2*p+1]);
    #pragma unroll
    for (int n = 1; n < 8; n++)
        #pragma unroll
        for (int p = 0; p < 4; p++) {
            float lo, hi; unpack2(acc[n][p], lo, hi);
            m[2*p]   = fmaxf(m[2*p], lo);
            m[2*p+1] = fmaxf(m[2*p+1], hi);
        }
    #pragma unroll
    for (int j = 0; j < 8; j++) red[ngrp * 68 + c0 + j] = m[j];
    __syncthreads();

    float mm = red[tid];
    #pragma unroll
    for (int r = 1; r < 8; r++) mm = fmaxf(mm, red[r * 68 + tid]);
    g_h2max[bs * HH + tid] = mm;
}

// ---------------- stage 3: bottleneck mlp3 + skip, write transposed ------
#define TS 16
__global__ __launch_bounds__(256) void stage3_kernel(
    const float* __restrict__ w3a, const float* __restrict__ s3a, const float* __restrict__ t3a,
    const float* __restrict__ w3b, const float* __restrict__ s3b, const float* __restrict__ t3b,
    float* __restrict__ out)
{
    __shared__ float h2s[TS * HH];
    __shared__ float h3s[TS * H3];
    int t = threadIdx.x;
    int row0 = blockIdx.x * TS;

    for (int i = t; i < TS * HH; i += 256) h2s[i] = g_h2max[row0 * HH + i];
    __syncthreads();

    {
        float sc = s3a[t], bi = t3a[t];
        float acc[TS];
        #pragma unroll
        for (int r = 0; r < TS; r++) acc[r] = bi;
        #pragma unroll 4
        for (int i = 0; i < HH; i++) {
            float wv = w3a[i * H3 + t] * sc;
            #pragma unroll
            for (int r = 0; r < TS; r++) acc[r] += h2s[r * HH + i] * wv;
        }
        #pragma unroll
        for (int r = 0; r < TS; r++) h3s[r * H3 + t] = fmaxf(acc[r], 0.0f);
    }
    __syncthreads();

    {
        int c  = t & 63;
        int rg = t >> 6;
        float sc = s3b[c], bi = t3b[c];
        float acc[4];
        #pragma unroll
        for (int rr = 0; rr < 4; rr++) acc[rr] = bi;
        #pragma unroll 4
        for (int i = 0; i < H3; i++) {
            float wv = w3b[i * HH + c] * sc;
            #pragma unroll
            for (int rr = 0; rr < 4; rr++)
                acc[rr] += h3s[(rg * 4 + rr) * H3 + i] * wv;
        }
        #pragma unroll
        for (int rr = 0; rr < 4; rr++) {
            int row = row0 + rg * 4 + rr;
            int b = row >> 10, s = row & 1023;
            float v = acc[rr] + g_newfeat[row * HH + c];
            out[OFF_OUT + ((b * HH + c) << 10) + s] = fmaxf(v, 0.0f);
        }
    }
}

// ---------------- launch ----------------
extern "C" void kernel_launch(void* const* d_in, const int* in_sizes, int n_in,
                              void* d_out, int out_size)
{
    const float* locs  = (const float*)d_in[0];
    const float* feats = (const float*)d_in[1];
    const float* boxes = (const float*)d_in[2];
    const int*   fps   = (const int*)d_in[3];
    const int*   nbr   = (const int*)d_in[4];
    const int*   nbr2  = (const int*)d_in[5];
    const float* w1a = (const float*)d_in[6];
    const float* s1a = (const float*)d_in[7];
    const float* t1a = (const float*)d_in[8];
    const float* w1b = (const float*)d_in[9];
    const float* s1b = (const float*)d_in[10];
    const float* t1b = (const float*)d_in[11];
    const float* w2  = (const float*)d_in[12];
    const float* s2  = (const float*)d_in[13];
    const float* t2  = (const float*)d_in[14];
    const float* w3a = (const float*)d_in[15];
    const float* s3a = (const float*)d_in[16];
    const float* t3a = (const float*)d_in[17];
    const float* w3b = (const float*)d_in[18];
    const float* s3b = (const float*)d_in[19];
    const float* t3b = (const float*)d_in[20];
    float* out = (float*)d_out;

    prep_kernel<<<(BB * NN + 255) / 256, 256>>>(feats, boxes);
    fps_kernel<<<(BB * SS + 255) / 256, 256>>>(locs, boxes, fps, out);
    stage1_kernel<<<BB * SS, 64>>>(locs, nbr, w1a, s1a, t1a, w1b, s1b, t1b);
    stage2_kernel<<<BB * SS, 64>>>(nbr2, w2, s2, t2);
    stage3_kernel<<<(BB * SS) / TS, 256>>>(w3a, s3a, t3a, w3b, s3b, t3b, out);
}

// round 5
// speedup vs baseline: 1.3357x; 1.1685x over previous
#include <cuda_runtime.h>
#include <cuda_bf16.h>

// ---------------- problem constants ----------------
#define BB 8
#define NN 131072
#define SS 1024
#define KK 64
#define CC 32
#define HH 64          // 2*C
#define D1 38          // C + 6
#define D2 70          // H + 6
#define H3 256         // 4*H

#define QPB 4          // queries per block (stage1/2)

// output layout (flattened concat of the 4 returned tensors)
#define OFF_LOCS  0
#define OFF_OUT   (BB*SS*3)                  // 24576
#define OFF_BOXES (OFF_OUT + BB*HH*SS)       // 548864
#define OFF_INDS  (OFF_BOXES + BB*SS*6)      // 598016

typedef unsigned long long ull;

// ---------------- f32x2 packed helpers (sm_100+) ----------------
__device__ __forceinline__ ull pack2(float lo, float hi) {
    ull r; asm("mov.b64 %0, {%1, %2};" : "=l"(r) : "f"(lo), "f"(hi)); return r;
}
__device__ __forceinline__ void unpack2(ull v, float& lo, float& hi) {
    asm("mov.b64 {%0, %1}, %2;" : "=f"(lo), "=f"(hi) : "l"(v));
}
__device__ __forceinline__ void fma2(ull& d, ull a, ull b) {
    asm("fma.rn.f32x2 %0, %1, %2, %0;" : "+l"(d) : "l"(a), "l"(b));
}

// ---------------- scratch (device globals; no allocation allowed) ----------
__device__ float g_feats_nc[BB * NN * CC];   // [B,N,C] transposed feats
__device__ float g_dimbox  [BB * NN * 3];
__device__ float g_fps_locs[BB * SS * 3];
__device__ float g_fps_dim [BB * SS * 3];
__device__ float g_newfeat [BB * SS * HH];   // stage1 output == identity
__device__ float g_h2max   [BB * SS * HH];   // stage2 output

// ---------------- prep: transpose feats, compute dim boxes ----------------
__global__ __launch_bounds__(256) void prep_kernel(
    const float* __restrict__ feats, const float* __restrict__ boxes)
{
    int idx = blockIdx.x * blockDim.x + threadIdx.x;   // over B*N
    if (idx >= BB * NN) return;
    int b = idx >> 17;
    int n = idx & (NN - 1);

    float tmp[CC];
    #pragma unroll
    for (int c = 0; c < CC; c++)
        tmp[c] = feats[(b * CC + c) * NN + n];

    float4* dst = (float4*)(g_feats_nc + ((size_t)idx << 5));
    #pragma unroll
    for (int q = 0; q < 8; q++)
        dst[q] = make_float4(tmp[4*q], tmp[4*q+1], tmp[4*q+2], tmp[4*q+3]);

    const float* bx = boxes + (size_t)idx * 6;
    float* dd = g_dimbox + (size_t)idx * 3;
    dd[0] = bx[3] - bx[0];
    dd[1] = bx[4] - bx[1];
    dd[2] = bx[5] - bx[2];
}

// ---------------- fps gather ----------
__global__ __launch_bounds__(256) void fps_kernel(
    const float* __restrict__ locs, const float* __restrict__ boxes,
    const int* __restrict__ fps_inds, float* __restrict__ out)
{
    int idx = blockIdx.x * blockDim.x + threadIdx.x;   // over B*S
    if (idx >= BB * SS) return;
    int b = idx >> 10;
    int j = fps_inds[idx];

    const float* lp = locs + ((size_t)b * NN + j) * 3;
    float l0 = lp[0], l1 = lp[1], l2 = lp[2];
    g_fps_locs[idx*3+0] = l0; g_fps_locs[idx*3+1] = l1; g_fps_locs[idx*3+2] = l2;
    out[OFF_LOCS + idx*3 + 0] = l0;
    out[OFF_LOCS + idx*3 + 1] = l1;
    out[OFF_LOCS + idx*3 + 2] = l2;

    const float* bx = boxes + ((size_t)b * NN + j) * 6;
    float b0 = bx[0], b1 = bx[1], b2 = bx[2], b3 = bx[3], b4 = bx[4], b5 = bx[5];
    g_fps_dim[idx*3+0] = b3 - b0;
    g_fps_dim[idx*3+1] = b4 - b1;
    g_fps_dim[idx*3+2] = b5 - b2;
    out[OFF_BOXES + idx*6 + 0] = b0;
    out[OFF_BOXES + idx*6 + 1] = b1;
    out[OFF_BOXES + idx*6 + 2] = b2;
    out[OFF_BOXES + idx*6 + 3] = b3;
    out[OFF_BOXES + idx*6 + 4] = b4;
    out[OFF_BOXES + idx*6 + 5] = b5;

    out[OFF_INDS + idx] = (float)j;
}

// ================= stage 1: QPB queries/block, shared weights ============
// smem floats: wa[1216] wb[2048] ba[32] bb[64] | per-q: g1[2432] h1[2176] red[544]
#define S1_BASE (D1*CC + CC*HH + CC + HH)       // 3360
#define S1_PERQ (D1*64 + CC*68 + 8*68)          // 5152
#define S1_SMEM ((S1_BASE + QPB*S1_PERQ) * 4)   // 95872 bytes

__global__ __launch_bounds__(64*QPB) void stage1_kernel(
    const float* __restrict__ locs, const int* __restrict__ nbr,
    const float* __restrict__ w1a, const float* __restrict__ s1a, const float* __restrict__ t1a,
    const float* __restrict__ w1b, const float* __restrict__ s1b, const float* __restrict__ t1b)
{
    extern __shared__ float sm[];
    float* wa_s = sm;                 // D1*CC
    float* wb_s = wa_s + D1*CC;       // CC*HH
    float* ba_s = wb_s + CC*HH;       // CC
    float* bb_s = ba_s + CC;          // HH
    int tid  = threadIdx.x;
    int q    = tid >> 6;
    int ltid = tid & 63;
    float* g1_s = sm + S1_BASE + q * S1_PERQ;   // D1*64
    float* h1_s = g1_s + D1*64;                 // CC*68
    float* red  = h1_s + CC*68;                 // 8*68

    int bs = blockIdx.x * QPB + q;
    int b  = bs >> 10;

    for (int i = tid; i < D1 * CC; i += 64*QPB) wa_s[i] = w1a[i] * s1a[i & 31];
    for (int i = tid; i < CC * HH; i += 64*QPB) wb_s[i] = w1b[i] * s1b[i & 63];
    if (tid < CC) ba_s[tid] = t1a[tid];
    if (tid < HH) bb_s[tid] = t1b[tid];

    // ---- fill g1_s[i][n]: thread = neighbor ----
    {
        int j = nbr[bs * KK + ltid];
        const float* lp = locs + ((size_t)b * NN + j) * 3;
        g1_s[0*64 + ltid] = (lp[0] - g_fps_locs[bs*3+0]) * 2.5f;
        g1_s[1*64 + ltid] = (lp[1] - g_fps_locs[bs*3+1]) * 2.5f;
        g1_s[2*64 + ltid] = (lp[2] - g_fps_locs[bs*3+2]) * 2.5f;
        const float* dp = g_dimbox + ((size_t)b * NN + j) * 3;
        g1_s[3*64 + ltid] = fabsf(dp[0] - g_fps_dim[bs*3+0]);
        g1_s[4*64 + ltid] = fabsf(dp[1] - g_fps_dim[bs*3+1]);
        g1_s[5*64 + ltid] = fabsf(dp[2] - g_fps_dim[bs*3+2]);
        const float4* fp = (const float4*)(g_feats_nc + (((size_t)b * NN + j) << 5));
        #pragma unroll
        for (int qq = 0; qq < 8; qq++) {
            float4 v = fp[qq];
            g1_s[(6+4*qq+0)*64 + ltid] = v.x;
            g1_s[(6+4*qq+1)*64 + ltid] = v.y;
            g1_s[(6+4*qq+2)*64 + ltid] = v.z;
            g1_s[(6+4*qq+3)*64 + ltid] = v.w;
        }
    }
    __syncthreads();

    int ngrp = ltid & 7, cgrp = ltid >> 3;
    int n0 = ngrp * 8;

    // ---- GEMM A: 38 -> 32, relu. Tile 8n x 4c. ----
    {
        int c0 = cgrp * 4;
        ull acc[8][2];
        ull bi0 = pack2(ba_s[c0+0], ba_s[c0+1]);
        ull bi1 = pack2(ba_s[c0+2], ba_s[c0+3]);
        #pragma unroll
        for (int n = 0; n < 8; n++) { acc[n][0] = bi0; acc[n][1] = bi1; }

        #pragma unroll 2
        for (int i = 0; i < D1; i++) {
            const float* gr = g1_s + i * 64 + n0;
            float4 ga = *(const float4*)gr;
            float4 gb = *(const float4*)(gr + 4);
            ulonglong2 wv = *(const ulonglong2*)(wa_s + i * CC + c0);
            ull g2[8] = { pack2(ga.x,ga.x), pack2(ga.y,ga.y), pack2(ga.z,ga.z), pack2(ga.w,ga.w),
                          pack2(gb.x,gb.x), pack2(gb.y,gb.y), pack2(gb.z,gb.z), pack2(gb.w,gb.w) };
            #pragma unroll
            for (int n = 0; n < 8; n++) {
                fma2(acc[n][0], g2[n], wv.x);
                fma2(acc[n][1], g2[n], wv.y);
            }
        }
        #pragma unroll
        for (int n = 0; n < 8; n++) {
            float v0, v1, v2, v3;
            unpack2(acc[n][0], v0, v1);
            unpack2(acc[n][1], v2, v3);
            h1_s[(c0+0)*68 + n0 + n] = fmaxf(v0, 0.0f);
            h1_s[(c0+1)*68 + n0 + n] = fmaxf(v1, 0.0f);
            h1_s[(c0+2)*68 + n0 + n] = fmaxf(v2, 0.0f);
            h1_s[(c0+3)*68 + n0 + n] = fmaxf(v3, 0.0f);
        }
    }
    __syncthreads();

    // ---- GEMM B: 32 -> 64, relu, max over K. Tile 8n x 8c. ----
    {
        int c0 = cgrp * 8;
        ull acc[8][4];
        ull bi[4];
        #pragma unroll
        for (int p = 0; p < 4; p++) bi[p] = pack2(bb_s[c0+2*p], bb_s[c0+2*p+1]);
        #pragma unroll
        for (int n = 0; n < 8; n++)
            #pragma unroll
            for (int p = 0; p < 4; p++) acc[n][p] = bi[p];

        #pragma unroll 2
        for (int i = 0; i < CC; i++) {
            const float* gr = h1_s + i * 68 + n0;
            float4 ga = *(const float4*)gr;
            float4 gb = *(const float4*)(gr + 4);
            ulonglong2 wv0 = *(const ulonglong2*)(wb_s + i * HH + c0);
            ulonglong2 wv1 = *(const ulonglong2*)(wb_s + i * HH + c0 + 4);
            ull w[4] = { wv0.x, wv0.y, wv1.x, wv1.y };
            ull g2[8] = { pack2(ga.x,ga.x), pack2(ga.y,ga.y), pack2(ga.z,ga.z), pack2(ga.w,ga.w),
                          pack2(gb.x,gb.x), pack2(gb.y,gb.y), pack2(gb.z,gb.z), pack2(gb.w,gb.w) };
            #pragma unroll
            for (int n = 0; n < 8; n++)
                #pragma unroll
                for (int p = 0; p < 4; p++) fma2(acc[n][p], g2[n], w[p]);
        }

        // local max over the 8 register-resident neighbors (relu deferred: monotone)
        float m[8];
        #pragma unroll
        for (int p = 0; p < 4; p++) unpack2(acc[0][p], m[2*p], m[2*p+1]);
        #pragma unroll
        for (int n = 1; n < 8; n++)
            #pragma unroll
            for (int p = 0; p < 4; p++) {
                float lo, hi; unpack2(acc[n][p], lo, hi);
                m[2*p]   = fmaxf(m[2*p], lo);
                m[2*p+1] = fmaxf(m[2*p+1], hi);
            }
        #pragma unroll
        for (int j = 0; j < 8; j++) red[ngrp * 68 + c0 + j] = m[j];
    }
    __syncthreads();

    float mm = red[ltid];
    #pragma unroll
    for (int r = 1; r < 8; r++) mm = fmaxf(mm, red[r * 68 + ltid]);
    g_newfeat[bs * HH + ltid] = fmaxf(mm, 0.0f);
}

// ================= stage 2: QPB queries/block, shared weights ============
// smem floats: w[4480] sb[64] | per-q: g[4480] red[544]
#define S2_BASE (D2*HH + HH)                    // 4544
#define S2_PERQ (D2*64 + 8*68)                  // 5024
#define S2_SMEM ((S2_BASE + QPB*S2_PERQ) * 4)   // 98560 bytes

__global__ __launch_bounds__(64*QPB) void stage2_kernel(
    const int* __restrict__ nbr2,
    const float* __restrict__ w2, const float* __restrict__ s2, const float* __restrict__ t2)
{
    extern __shared__ float sm[];
    float* w_s = sm;                  // D2*HH
    float* sb  = w_s + D2*HH;         // HH
    int tid  = threadIdx.x;
    int q    = tid >> 6;
    int ltid = tid & 63;
    float* g_s = sm + S2_BASE + q * S2_PERQ;   // D2*64
    float* red = g_s + D2*64;                  // 8*68

    int bs = blockIdx.x * QPB + q;
    int b  = bs >> 10;

    for (int i = tid; i < D2 * HH; i += 64*QPB) w_s[i] = w2[i] * s2[i & 63];
    if (tid < HH) sb[tid] = t2[tid];

    // ---- fill g_s[i][n]: thread = neighbor ----
    {
        int j  = nbr2[bs * KK + ltid];
        int fj = (b << 10) + j;
        g_s[0*64 + ltid] = (g_fps_locs[fj*3+0] - g_fps_locs[bs*3+0]) * 1.25f;
        g_s[1*64 + ltid] = (g_fps_locs[fj*3+1] - g_fps_locs[bs*3+1]) * 1.25f;
        g_s[2*64 + ltid] = (g_fps_locs[fj*3+2] - g_fps_locs[bs*3+2]) * 1.25f;
        g_s[3*64 + ltid] = fabsf(g_fps_dim[fj*3+0] - g_fps_dim[bs*3+0]);
        g_s[4*64 + ltid] = fabsf(g_fps_dim[fj*3+1] - g_fps_dim[bs*3+1]);
        g_s[5*64 + ltid] = fabsf(g_fps_dim[fj*3+2] - g_fps_dim[bs*3+2]);
        const float4* fp = (const float4*)(g_newfeat + (size_t)fj * HH);
        #pragma unroll
        for (int qq = 0; qq < 16; qq++) {
            float4 v = fp[qq];
            g_s[(6+4*qq+0)*64 + ltid] = v.x;
            g_s[(6+4*qq+1)*64 + ltid] = v.y;
            g_s[(6+4*qq+2)*64 + ltid] = v.z;
            g_s[(6+4*qq+3)*64 + ltid] = v.w;
        }
    }
    __syncthreads();

    int ngrp = ltid & 7, cgrp = ltid >> 3;
    int n0 = ngrp * 8, c0 = cgrp * 8;

    ull acc[8][4];
    {
        ull bi[4];
        #pragma unroll
        for (int p = 0; p < 4; p++) bi[p] = pack2(sb[c0+2*p], sb[c0+2*p+1]);
        #pragma unroll
        for (int n = 0; n < 8; n++)
            #pragma unroll
            for (int p = 0; p < 4; p++) acc[n][p] = bi[p];
    }

    #pragma unroll 2
    for (int i = 0; i < D2; i++) {
        const float* gr = g_s + i * 64 + n0;
        float4 ga = *(const float4*)gr;
        float4 gb = *(const float4*)(gr + 4);
        ulonglong2 wv0 = *(const ulonglong2*)(w_s + i * HH + c0);
        ulonglong2 wv1 = *(const ulonglong2*)(w_s + i * HH + c0 + 4);
        ull w[4] = { wv0.x, wv0.y, wv1.x, wv1.y };
        ull g2[8] = { pack2(ga.x,ga.x), pack2(ga.y,ga.y), pack2(ga.z,ga.z), pack2(ga.w,ga.w),
                      pack2(gb.x,gb.x), pack2(gb.y,gb.y), pack2(gb.z,gb.z), pack2(gb.w,gb.w) };
        #pragma unroll
        for (int n = 0; n < 8; n++)
            #pragma unroll
            for (int p = 0; p < 4; p++) fma2(acc[n][p], g2[n], w[p]);
    }

    // max over 8 local neighbors (no relu in stage 2)
    float m[8];
    #pragma unroll
    for (int p = 0; p < 4; p++) unpack2(acc[0][p], m[2*p], m[2*p+1]);
    #pragma unroll
    for (int n = 1; n < 8; n++)
        #pragma unroll
        for (int p = 0; p < 4; p++) {
            float lo, hi; unpack2(acc[n][p], lo, hi);
            m[2*p]   = fmaxf(m[2*p], lo);
            m[2*p+1] = fmaxf(m[2*p+1], hi);
        }
    #pragma unroll
    for (int j = 0; j < 8; j++) red[ngrp * 68 + c0 + j] = m[j];
    __syncthreads();

    float mm = red[ltid];
    #pragma unroll
    for (int r = 1; r < 8; r++) mm = fmaxf(mm, red[r * 68 + ltid]);
    g_h2max[bs * HH + ltid] = mm;
}

// ---------------- stage 3: bottleneck mlp3 + skip, write transposed ------
#define TS 16
__global__ __launch_bounds__(256) void stage3_kernel(
    const float* __restrict__ w3a, const float* __restrict__ s3a, const float* __restrict__ t3a,
    const float* __restrict__ w3b, const float* __restrict__ s3b, const float* __restrict__ t3b,
    float* __restrict__ out)
{
    __shared__ float h2s[TS * HH];
    __shared__ float h3s[TS * H3];
    int t = threadIdx.x;
    int row0 = blockIdx.x * TS;

    for (int i = t; i < TS * HH; i += 256) h2s[i] = g_h2max[row0 * HH + i];
    __syncthreads();

    {
        float sc = s3a[t], bi = t3a[t];
        float acc[TS];
        #pragma unroll
        for (int r = 0; r < TS; r++) acc[r] = bi;
        #pragma unroll 4
        for (int i = 0; i < HH; i++) {
            float wv = w3a[i * H3 + t] * sc;
            #pragma unroll
            for (int r = 0; r < TS; r++) acc[r] += h2s[r * HH + i] * wv;
        }
        #pragma unroll
        for (int r = 0; r < TS; r++) h3s[r * H3 + t] = fmaxf(acc[r], 0.0f);
    }
    __syncthreads();

    {
        int c  = t & 63;
        int rg = t >> 6;
        float sc = s3b[c], bi = t3b[c];
        float acc[4];
        #pragma unroll
        for (int rr = 0; rr < 4; rr++) acc[rr] = bi;
        #pragma unroll 4
        for (int i = 0; i < H3; i++) {
            float wv = w3b[i * HH + c] * sc;
            #pragma unroll
            for (int rr = 0; rr < 4; rr++)
                acc[rr] += h3s[(rg * 4 + rr) * H3 + i] * wv;
        }
        #pragma unroll
        for (int rr = 0; rr < 4; rr++) {
            int row = row0 + rg * 4 + rr;
            int b = row >> 10, s = row & 1023;
            float v = acc[rr] + g_newfeat[row * HH + c];
            out[OFF_OUT + ((b * HH + c) << 10) + s] = fmaxf(v, 0.0f);
        }
    }
}

// ---------------- launch ----------------
extern "C" void kernel_launch(void* const* d_in, const int* in_sizes, int n_in,
                              void* d_out, int out_size)
{
    const float* locs  = (const float*)d_in[0];
    const float* feats = (const float*)d_in[1];
    const float* boxes = (const float*)d_in[2];
    const int*   fps   = (const int*)d_in[3];
    const int*   nbr   = (const int*)d_in[4];
    const int*   nbr2  = (const int*)d_in[5];
    const float* w1a = (const float*)d_in[6];
    const float* s1a = (const float*)d_in[7];
    const float* t1a = (const float*)d_in[8];
    const float* w1b = (const float*)d_in[9];
    const float* s1b = (const float*)d_in[10];
    const float* t1b = (const float*)d_in[11];
    const float* w2  = (const float*)d_in[12];
    const float* s2  = (const float*)d_in[13];
    const float* t2  = (const float*)d_in[14];
    const float* w3a = (const float*)d_in[15];
    const float* s3a = (const float*)d_in[16];
    const float* t3a = (const float*)d_in[17];
    const float* w3b = (const float*)d_in[18];
    const float* s3b = (const float*)d_in[19];
    const float* t3b = (const float*)d_in[20];
    float* out = (float*)d_out;

    cudaFuncSetAttribute(stage1_kernel, cudaFuncAttributeMaxDynamicSharedMemorySize, S1_SMEM);
    cudaFuncSetAttribute(stage2_kernel, cudaFuncAttributeMaxDynamicSharedMemorySize, S2_SMEM);

    prep_kernel<<<(BB * NN + 255) / 256, 256>>>(feats, boxes);
    fps_kernel<<<(BB * SS + 255) / 256, 256>>>(locs, boxes, fps, out);
    stage1_kernel<<<BB * SS / QPB, 64*QPB, S1_SMEM>>>(locs, nbr, w1a, s1a, t1a, w1b, s1b, t1b);
    stage2_kernel<<<BB * SS / QPB, 64*QPB, S2_SMEM>>>(nbr2, w2, s2, t2);
    stage3_kernel<<<(BB * SS) / TS, 256>>>(w3a, s3a, t3a, w3b, s3b, t3b, out);
}